// round 8
// baseline (speedup 1.0000x reference)
#include <cuda_runtime.h>

#define RB 64
#define RT 2048
#define RD 256
#define RV 256

// ---- device-global scratch (allocation-free per harness rules) ----
static __device__ float g_EWx[RV * RD];                 // E @ Wx^T   [tok][e]
static __device__ float g_EWg[RV * RD];                 // sigmoid(E @ Wz^T)
static __device__ float g_y[(size_t)RB * RT * RD];      // gated hidden states

// packed fp32x2 FMA: 2 independent bit-exact fp32 FMAs per instruction
#define FMA2(acc, h, w) \
    asm("fma.rn.f32x2 %0, %1, %2, %0;" : "+l"(acc) : "l"(h), "l"(w))

__device__ __forceinline__ float f2lo(unsigned long long v) {
    return __uint_as_float((unsigned)v);
}
__device__ __forceinline__ float f2hi(unsigned long long v) {
    return __uint_as_float((unsigned)(v >> 32));
}

// ============================================================
// Kernel 1: token tables (V=256 -> projections depend only on token id)
// ============================================================
__global__ void precompute_kernel(const float* __restrict__ E,
                                  const float* __restrict__ Wxw,
                                  const float* __restrict__ Wzw) {
    __shared__ __align__(16) float er[RD];
    const int v = blockIdx.x & (RV - 1);
    const int which = blockIdx.x >> 8;
    const float* __restrict__ W = which ? Wzw : Wxw;
    const int e = threadIdx.x;
    er[e] = E[v * RD + e];
    __syncthreads();
    const float4* w4 = (const float4*)(W + e * RD);
    const float4* e4 = (const float4*)er;
    float acc = 0.f;
#pragma unroll 16
    for (int q = 0; q < RD / 4; q++) {
        float4 a = e4[q];
        float4 b = w4[q];
        acc += a.x * b.x; acc += a.y * b.y; acc += a.z * b.z; acc += a.w * b.w;
    }
    if (which) g_EWg[v * RD + e] = 1.f / (1.f + expf(-acc));
    else       g_EWx[v * RD + e] = acc;
}

// ============================================================
// Kernel 2: sequential scan, 2-CTA cluster per batch element.
// CTA c owns output rows [c*128, +128). Thread t: row r = t>>2,
// k-chunk q = t&3 (64 k over the full 256-wide h). Wh slice = 32
// packed f32x2 registers. h is exchanged (not partials): writers push
// new h to the peer right after tanh, so the DSMEM latency overlaps
// the step tail. Per step: uniform mbar fast-wait (peer half) ->
// 32 FFMA2 -> 2x shfl.bfly reduce -> writer lane: tanh, y, local h
// store, remote h store + release-arrive (count-128 peer mbar) ->
// ONE __syncthreads (gates local h-half).
// ============================================================
#define SCAN_THREADS 512
#define SCAN_PAD_BYTES (120 * 1024)    // occupancy limiter: 1 CTA/SM

__device__ __forceinline__ float tanh_acc(float x) {
    x = fminf(fmaxf(x, -15.f), 15.f);
    float e = __expf(2.f * x);
    return (e - 1.f) / (e + 1.f);
}

__device__ __forceinline__ unsigned smem_u32(const void* p) {
    return (unsigned)__cvta_generic_to_shared(p);
}

__global__ __launch_bounds__(SCAN_THREADS, 1) __cluster_dims__(2, 1, 1)
void scan_kernel(const int* __restrict__ tokens, const float* __restrict__ Whw) {
    __shared__ __align__(16) float sm_hown[2][128];    // own half, dbl-buf
    __shared__ __align__(16) float sm_hrecv[2][128];   // peer half, dbl-buf
    __shared__ __align__(8)  unsigned long long mbar[2];
    extern __shared__ float sm_pad[];                  // unused (occupancy)

    const int b    = blockIdx.x >> 1;
    const int c    = blockIdx.x & 1;       // cluster rank
    const int peer = c ^ 1;
    const int t = threadIdx.x;
    const int r = t >> 2;                  // local output row 0..127
    const int q = t & 3;                   // k chunk 0..3 (global k = q*64..)

    if (t == 0) {
        unsigned m0 = smem_u32(&mbar[0]);
        unsigned m1 = smem_u32(&mbar[1]);
        asm volatile("mbarrier.init.shared.b64 [%0], 128;" :: "r"(m0) : "memory");
        asm volatile("mbarrier.init.shared.b64 [%0], 128;" :: "r"(m1) : "memory");
    }
    if (t < 128) { sm_hown[0][t] = 0.f; sm_hrecv[0][t] = 0.f; }
    __syncthreads();
    // cluster barrier: peers' mbarriers live before any remote traffic
    asm volatile("barrier.cluster.arrive.aligned;" ::: "memory");
    asm volatile("barrier.cluster.wait.aligned;"   ::: "memory");

    // ---- Wh row j = c*128+r, k in [q*64, +64): 32 packed f32x2 regs ----
    const int j = c * 128 + r;
    unsigned long long whp[32];
    {
        const ulonglong2* wr = (const ulonglong2*)(Whw + j * RD + q * 64);
#pragma unroll
        for (int i = 0; i < 16; i++) {
            ulonglong2 vv = wr[i];
            whp[2 * i]     = vv.x;
            whp[2 * i + 1] = vv.y;
        }
    }

    // h source for my chunk: own iff this chunk's k-half == my rank
    // within-half offset = (q&1)*64
    const ulonglong2* hb[2];
    if ((q >> 1) == c) {
        hb[0] = (const ulonglong2*)(&sm_hown[0][(q & 1) * 64]);
        hb[1] = (const ulonglong2*)(&sm_hown[1][(q & 1) * 64]);
    } else {
        hb[0] = (const ulonglong2*)(&sm_hrecv[0][(q & 1) * 64]);
        hb[1] = (const ulonglong2*)(&sm_hrecv[1][(q & 1) * 64]);
    }

    // writer-lane remote addresses (q==0): peer's sm_hrecv[.][r] and mbars
    unsigned rrecv[2], rmbar[2];
    {
        unsigned a0 = smem_u32(&mbar[0]), a1 = smem_u32(&mbar[1]);
        asm("mapa.shared::cluster.u32 %0, %1, %2;" : "=r"(rmbar[0]) : "r"(a0), "r"(peer));
        asm("mapa.shared::cluster.u32 %0, %1, %2;" : "=r"(rmbar[1]) : "r"(a1), "r"(peer));
        unsigned b0 = smem_u32(&sm_hrecv[0][r]);
        unsigned b1 = smem_u32(&sm_hrecv[1][r]);
        asm("mapa.shared::cluster.u32 %0, %1, %2;" : "=r"(rrecv[0]) : "r"(b0), "r"(peer));
        asm("mapa.shared::cluster.u32 %0, %1, %2;" : "=r"(rrecv[1]) : "r"(b1), "r"(peer));
    }
    const unsigned lmbar0 = smem_u32(&mbar[0]);
    const unsigned lmbar1 = smem_u32(&mbar[1]);

    const int* tb = tokens + b * RT;
    float*     yb = g_y + (size_t)b * RT * RD + c * 128;

    int pp0 = 0, pp1 = 0;                  // wait parity per buffer
    int tok = tb[0];
    float wxv = 0.f, gv = 0.f;
    if (q == 0) {
        wxv = __ldg(g_EWx + tok * RD + c * 128 + r);
        gv  = __ldg(g_EWg + tok * RD + c * 128 + r);
    }

    for (int step = 0; step < RT; step++) {
        const int buf = step & 1;
        const int nb  = buf ^ 1;
        const int ntok = (step + 1 < RT) ? tb[step + 1] : 0;

        // uniform wait for the peer h-half (arrival normally already landed)
        if (step > 0) {
            const unsigned lmb = buf ? lmbar1 : lmbar0;
            const unsigned par = (unsigned)(buf ? pp1 : pp0);
            unsigned done;
            do {
                asm volatile(
                    "{.reg .pred p;\n\t"
                    "mbarrier.try_wait.parity.acquire.cluster.shared::cta.b64 p, [%1], %2, 0x989680;\n\t"
                    "selp.b32 %0, 1, 0, p;}"
                    : "=r"(done) : "r"(lmb), "r"(par) : "memory");
            } while (!done);
            if (buf) pp1 ^= 1; else pp0 ^= 1;
        }

        // matvec: 32 packed FFMA2 over my 64-k chunk
        const ulonglong2* hp = hb[buf];
        unsigned long long a0 = 0ull, a1 = 0ull, a2 = 0ull, a3 = 0ull;
#pragma unroll
        for (int i = 0; i < 16; i += 2) {
            ulonglong2 h0 = hp[i];
            ulonglong2 h1 = hp[i + 1];
            FMA2(a0, h0.x, whp[2 * i]);
            FMA2(a1, h0.y, whp[2 * i + 1]);
            FMA2(a2, h1.x, whp[2 * i + 2]);
            FMA2(a3, h1.y, whp[2 * i + 3]);
        }
        float s = ((f2lo(a0) + f2hi(a0)) + (f2lo(a1) + f2hi(a1))) +
                  ((f2lo(a2) + f2hi(a2)) + (f2lo(a3) + f2hi(a3)));
        // 4-lane butterfly reduce (lanes of a row share a warp)
        s += __shfl_xor_sync(0xffffffffu, s, 1);
        s += __shfl_xor_sync(0xffffffffu, s, 2);

        if (q == 0) {
            float hn = tanh_acc(wxv + s);
            yb[(size_t)step * RD + r] = hn * gv;
            sm_hown[nb][r] = hn;                       // local half, next step
            // push h to peer's recv buffer for ITS next step
            asm volatile("st.shared::cluster.f32 [%0], %1;"
                         :: "r"(rrecv[nb]), "f"(hn) : "memory");
            asm volatile("mbarrier.arrive.release.cluster.shared::cluster.b64 _, [%0];"
                         :: "r"(rmbar[nb]) : "memory");
            // prefetch next token rows (latency hidden under next step)
            wxv = __ldg(g_EWx + ntok * RD + c * 128 + r);
            gv  = __ldg(g_EWg + ntok * RD + c * 128 + r);
        }
        __syncthreads();                               // gates sm_hown[nb]
        tok = ntok;
    }

    // drain: no CTA exits while the peer may still arrive on its mbars
    asm volatile("barrier.cluster.arrive.aligned;" ::: "memory");
    asm volatile("barrier.cluster.wait.aligned;"   ::: "memory");
    (void)sm_pad;
}

// ============================================================
// Kernel 3: tied head.  out[m][v] = sum_d Y[m][d] * E[v][d]
// 128x128x16 smem-tiled GEMM, 8x8 microtiles, FFMA2 inner product.
// ============================================================
#define HT 256
__global__ __launch_bounds__(HT, 2)
void head_kernel(const float* __restrict__ E, float* __restrict__ out) {
    __shared__ __align__(16) float As[16][128 + 4];
    __shared__ __align__(16) float Bs[16][128 + 4];
    const float* __restrict__ Y = g_y;
    const int m0 = blockIdx.y * 128;
    const int n0 = blockIdx.x * 128;
    const int tid = threadIdx.x;
    const int tx = tid & 15, ty = tid >> 4;

    unsigned long long cd[8][4];           // 8 rows x 4 packed col-pairs
#pragma unroll
    for (int i = 0; i < 8; i++)
#pragma unroll
        for (int jj = 0; jj < 4; jj++) cd[i][jj] = 0ull;

    for (int kk = 0; kk < RD; kk += 16) {
#pragma unroll
        for (int l = 0; l < 2; l++) {
            int idx = tid + l * HT;
            int m   = idx >> 2;
            int kq  = idx & 3;
            float4 av = *(const float4*)(Y + (size_t)(m0 + m) * RD + kk + kq * 4);
            As[kq * 4 + 0][m] = av.x; As[kq * 4 + 1][m] = av.y;
            As[kq * 4 + 2][m] = av.z; As[kq * 4 + 3][m] = av.w;
            float4 bv = *(const float4*)(E + (size_t)(n0 + m) * RD + kk + kq * 4);
            Bs[kq * 4 + 0][m] = bv.x; Bs[kq * 4 + 1][m] = bv.y;
            Bs[kq * 4 + 2][m] = bv.z; Bs[kq * 4 + 3][m] = bv.w;
        }
        __syncthreads();
#pragma unroll
        for (int k = 0; k < 16; k++) {
            float a[8];
            *(float4*)(a)     = *(const float4*)(&As[k][ty * 8]);
            *(float4*)(a + 4) = *(const float4*)(&As[k][ty * 8 + 4]);
            ulonglong2 b01 = *(const ulonglong2*)(&Bs[k][tx * 8]);
            ulonglong2 b23 = *(const ulonglong2*)(&Bs[k][tx * 8 + 4]);
            unsigned long long bp0 = b01.x, bp1 = b01.y;
            unsigned long long bp2 = b23.x, bp3 = b23.y;
#pragma unroll
            for (int i = 0; i < 8; i++) {
                unsigned long long ad;
                unsigned au = __float_as_uint(a[i]);
                asm("mov.b64 %0, {%1, %1};" : "=l"(ad) : "r"(au));
                FMA2(cd[i][0], ad, bp0);
                FMA2(cd[i][1], ad, bp1);
                FMA2(cd[i][2], ad, bp2);
                FMA2(cd[i][3], ad, bp3);
            }
        }
        __syncthreads();
    }
#pragma unroll
    for (int i = 0; i < 8; i++) {
        float* orow = out + (size_t)(m0 + ty * 8 + i) * RV + n0 + tx * 8;
        *(float4*)(orow)     = make_float4(f2lo(cd[i][0]), f2hi(cd[i][0]),
                                           f2lo(cd[i][1]), f2hi(cd[i][1]));
        *(float4*)(orow + 4) = make_float4(f2lo(cd[i][2]), f2hi(cd[i][2]),
                                           f2lo(cd[i][3]), f2hi(cd[i][3]));
    }
}

// ============================================================
extern "C" void kernel_launch(void* const* d_in, const int* in_sizes, int n_in,
                              void* d_out, int out_size) {
    const int*   tokens = (const int*)  d_in[0];
    const float* E      = (const float*)d_in[1];
    const float* Wxw    = (const float*)d_in[2];
    const float* Whw    = (const float*)d_in[3];
    const float* Wzw    = (const float*)d_in[4];
    float* out = (float*)d_out;

    cudaFuncSetAttribute(scan_kernel,
                         cudaFuncAttributeMaxDynamicSharedMemorySize,
                         SCAN_PAD_BYTES);

    precompute_kernel<<<2 * RV, RD>>>(E, Wxw, Wzw);
    scan_kernel<<<2 * RB, SCAN_THREADS, SCAN_PAD_BYTES>>>(tokens, Whw);
    head_kernel<<<dim3(RV / 128, (RB * RT) / 128), HT>>>(E, out);
}

// round 10
// speedup vs baseline: 2.3212x; 2.3212x over previous
#include <cuda_runtime.h>

#define RB 64
#define RT 2048
#define RD 256
#define RV 256

// ---- device-global scratch (allocation-free per harness rules) ----
static __device__ float g_EWx[RV * RD];                 // E @ Wx^T   [tok][e]
static __device__ float g_EWg[RV * RD];                 // sigmoid(E @ Wz^T)
static __device__ float g_y[(size_t)RB * RT * RD];      // gated hidden states

typedef unsigned long long ull;

// packed fp32x2 FMA: 2 independent bit-exact fp32 FMAs per instruction
#define FMA2(acc, h, w) \
    asm("fma.rn.f32x2 %0, %1, %2, %0;" : "+l"(acc) : "l"(h), "l"(w))

__device__ __forceinline__ float f2lo(ull v) {
    return __uint_as_float((unsigned)v);
}
__device__ __forceinline__ float f2hi(ull v) {
    return __uint_as_float((unsigned)(v >> 32));
}

// ============================================================
// Kernel 1: token tables (V=256 -> projections depend only on token id)
// ============================================================
__global__ void precompute_kernel(const float* __restrict__ E,
                                  const float* __restrict__ Wxw,
                                  const float* __restrict__ Wzw) {
    __shared__ __align__(16) float er[RD];
    const int v = blockIdx.x & (RV - 1);
    const int which = blockIdx.x >> 8;
    const float* __restrict__ W = which ? Wzw : Wxw;
    const int e = threadIdx.x;
    er[e] = E[v * RD + e];
    __syncthreads();
    const float4* w4 = (const float4*)(W + e * RD);
    const float4* e4 = (const float4*)er;
    float acc = 0.f;
#pragma unroll 16
    for (int q = 0; q < RD / 4; q++) {
        float4 a = e4[q];
        float4 b = w4[q];
        acc += a.x * b.x; acc += a.y * b.y; acc += a.z * b.z; acc += a.w * b.w;
    }
    if (which) g_EWg[v * RD + e] = 1.f / (1.f + expf(-acc));
    else       g_EWx[v * RD + e] = acc;
}

// ============================================================
// Kernel 2: sequential scan. ONE CTA per batch element (no cluster,
// no mbarriers). 512 threads: row r = t>>1, k-half = t&1 (128 k each,
// i.e. 64 packed f32x2 pairs = 32 ulonglong2 vectors of h).
// Wh slice per thread: pairs 0..47 in registers (96 floats),
// pairs 48..63 in SMEM ([pair][thread] layout, conflict-free LDS.64).
// Per step: 32x LDS.128 h (2 broadcast address streams on disjoint
// banks via the 132-float half stride) -> 64 FFMA2 -> 1 shfl.bfly
// pair-reduce -> even lane: tanh, y store, h store into next buffer,
// next-token prefetch -> ONE __syncthreads.
// ============================================================
#define SCAN_THREADS 512
#define WH_REG_PAIRS 48               // 96 floats in registers
#define WH_SM_PAIRS  16               // 32 floats in SMEM
#define H_HALF_STRIDE 132             // floats; 528B: 16B-aligned, +4 banks
#define H_BUF_STRIDE  (2 * H_HALF_STRIDE)   // 264 floats per buffer
#define SCAN_SMEM_BYTES (WH_SM_PAIRS * SCAN_THREADS * 8 + 2 * H_BUF_STRIDE * 4)

__device__ __forceinline__ float tanh_acc(float x) {
    x = fminf(fmaxf(x, -15.f), 15.f);
    float e = __expf(2.f * x);
    return (e - 1.f) / (e + 1.f);
}

__global__ __launch_bounds__(SCAN_THREADS, 1)
void scan_kernel(const int* __restrict__ tokens, const float* __restrict__ Whw) {
    extern __shared__ __align__(16) ull dynsm[];
    ull*   sm_whs = dynsm;                                   // [pair][thread]
    float* sm_h   = (float*)(dynsm + WH_SM_PAIRS * SCAN_THREADS);

    const int b    = blockIdx.x;
    const int t    = threadIdx.x;
    const int r    = t >> 1;            // output row 0..255
    const int half = t & 1;             // k-half: k in [half*128, +128)

    // ---- load Wh row r, my k-half ----
    // floats [0..95] -> 48 register pairs; floats [96..127] -> 16 SMEM pairs
    const float* wrow = Whw + r * RD + half * 128;
    ull whp[WH_REG_PAIRS];
    {
        const ulonglong2* wr = (const ulonglong2*)wrow;
#pragma unroll
        for (int i = 0; i < WH_REG_PAIRS / 2; i++) {   // i = 0..23
            ulonglong2 vv = wr[i];
            whp[2 * i]     = vv.x;
            whp[2 * i + 1] = vv.y;
        }
    }
#pragma unroll
    for (int p = 0; p < WH_SM_PAIRS; p++)
        sm_whs[p * SCAN_THREADS + t] = ((const ull*)wrow)[WH_REG_PAIRS + p];

    for (int i = t; i < 2 * H_BUF_STRIDE; i += SCAN_THREADS) sm_h[i] = 0.f;
    __syncthreads();

    const float* hbase = sm_h + half * H_HALF_STRIDE;
    const ull*   wsp   = sm_whs + t;                  // stride SCAN_THREADS
    const int*   tb    = tokens + b * RT;
    float*       yb    = g_y + (size_t)b * RT * RD;
    const int    hoff  = (r >> 7) * H_HALF_STRIDE + (r & 127);  // h write slot

    int tok = tb[0];
    float wxv = 0.f, gv = 0.f;
    if (half == 0) {
        wxv = __ldg(g_EWx + tok * RD + r);
        gv  = __ldg(g_EWg + tok * RD + r);
    }

    for (int step = 0; step < RT; step++) {
        const int buf = step & 1;
        // hp[0..31]: 32 x 16B vectors = 128 floats of h for my k-half
        const ulonglong2* hp = (const ulonglong2*)(hbase + buf * H_BUF_STRIDE);
        const int ntok = (step + 1 < RT) ? tb[step + 1] : 0;

        ull a0 = 0ull, a1 = 0ull, a2 = 0ull, a3 = 0ull;
        // register Wh part: hp[0..23]  (48 pairs) x whp[0..47]
#pragma unroll
        for (int i = 0; i < 12; i++) {
            ulonglong2 h0 = hp[2 * i];
            ulonglong2 h1 = hp[2 * i + 1];
            FMA2(a0, h0.x, whp[4 * i + 0]);
            FMA2(a1, h0.y, whp[4 * i + 1]);
            FMA2(a2, h1.x, whp[4 * i + 2]);
            FMA2(a3, h1.y, whp[4 * i + 3]);
        }
        // SMEM Wh part: hp[24..31]  (16 pairs) x SMEM pairs 0..15
#pragma unroll
        for (int i = 0; i < 8; i++) {
            ulonglong2 hv = hp[24 + i];
            FMA2(a0, hv.x, wsp[(2 * i + 0) * SCAN_THREADS]);
            FMA2(a1, hv.y, wsp[(2 * i + 1) * SCAN_THREADS]);
        }
        float s = ((f2lo(a0) + f2hi(a0)) + (f2lo(a1) + f2hi(a1))) +
                  ((f2lo(a2) + f2hi(a2)) + (f2lo(a3) + f2hi(a3)));
        s += __shfl_xor_sync(0xffffffffu, s, 1);       // pair reduce

        if (half == 0) {
            float hn = tanh_acc(wxv + s);
            yb[(size_t)step * RD + r] = hn * gv;       // 64B/warp coalesced
            sm_h[(buf ^ 1) * H_BUF_STRIDE + hoff] = hn;
            // prefetch next token rows (consumed one step later)
            wxv = __ldg(g_EWx + ntok * RD + r);
            gv  = __ldg(g_EWg + ntok * RD + r);
        }
        __syncthreads();                               // gates next buffer
        tok = ntok;
    }
}

// ============================================================
// Kernel 3: tied head.  out[m][v] = sum_d Y[m][d] * E[v][d]
// 128x128x16 smem-tiled GEMM, 8x8 microtiles, FFMA2 inner product.
// ============================================================
#define HT 256
__global__ __launch_bounds__(HT, 2)
void head_kernel(const float* __restrict__ E, float* __restrict__ out) {
    __shared__ __align__(16) float As[16][128 + 4];
    __shared__ __align__(16) float Bs[16][128 + 4];
    const float* __restrict__ Y = g_y;
    const int m0 = blockIdx.y * 128;
    const int n0 = blockIdx.x * 128;
    const int tid = threadIdx.x;
    const int tx = tid & 15, ty = tid >> 4;

    ull cd[8][4];                          // 8 rows x 4 packed col-pairs
#pragma unroll
    for (int i = 0; i < 8; i++)
#pragma unroll
        for (int jj = 0; jj < 4; jj++) cd[i][jj] = 0ull;

    for (int kk = 0; kk < RD; kk += 16) {
#pragma unroll
        for (int l = 0; l < 2; l++) {
            int idx = tid + l * HT;
            int m   = idx >> 2;
            int kq  = idx & 3;
            float4 av = *(const float4*)(Y + (size_t)(m0 + m) * RD + kk + kq * 4);
            As[kq * 4 + 0][m] = av.x; As[kq * 4 + 1][m] = av.y;
            As[kq * 4 + 2][m] = av.z; As[kq * 4 + 3][m] = av.w;
            float4 bv = *(const float4*)(E + (size_t)(n0 + m) * RD + kk + kq * 4);
            Bs[kq * 4 + 0][m] = bv.x; Bs[kq * 4 + 1][m] = bv.y;
            Bs[kq * 4 + 2][m] = bv.z; Bs[kq * 4 + 3][m] = bv.w;
        }
        __syncthreads();
#pragma unroll
        for (int k = 0; k < 16; k++) {
            float a[8];
            *(float4*)(a)     = *(const float4*)(&As[k][ty * 8]);
            *(float4*)(a + 4) = *(const float4*)(&As[k][ty * 8 + 4]);
            ulonglong2 b01 = *(const ulonglong2*)(&Bs[k][tx * 8]);
            ulonglong2 b23 = *(const ulonglong2*)(&Bs[k][tx * 8 + 4]);
            ull bp0 = b01.x, bp1 = b01.y;
            ull bp2 = b23.x, bp3 = b23.y;
#pragma unroll
            for (int i = 0; i < 8; i++) {
                ull ad;
                unsigned au = __float_as_uint(a[i]);
                asm("mov.b64 %0, {%1, %1};" : "=l"(ad) : "r"(au));
                FMA2(cd[i][0], ad, bp0);
                FMA2(cd[i][1], ad, bp1);
                FMA2(cd[i][2], ad, bp2);
                FMA2(cd[i][3], ad, bp3);
            }
        }
        __syncthreads();
    }
#pragma unroll
    for (int i = 0; i < 8; i++) {
        float* orow = out + (size_t)(m0 + ty * 8 + i) * RV + n0 + tx * 8;
        *(float4*)(orow)     = make_float4(f2lo(cd[i][0]), f2hi(cd[i][0]),
                                           f2lo(cd[i][1]), f2hi(cd[i][1]));
        *(float4*)(orow + 4) = make_float4(f2lo(cd[i][2]), f2hi(cd[i][2]),
                                           f2lo(cd[i][3]), f2hi(cd[i][3]));
    }
}

// ============================================================
extern "C" void kernel_launch(void* const* d_in, const int* in_sizes, int n_in,
                              void* d_out, int out_size) {
    const int*   tokens = (const int*)  d_in[0];
    const float* E      = (const float*)d_in[1];
    const float* Wxw    = (const float*)d_in[2];
    const float* Whw    = (const float*)d_in[3];
    const float* Wzw    = (const float*)d_in[4];
    float* out = (float*)d_out;

    cudaFuncSetAttribute(scan_kernel,
                         cudaFuncAttributeMaxDynamicSharedMemorySize,
                         SCAN_SMEM_BYTES);

    precompute_kernel<<<2 * RV, RD>>>(E, Wxw, Wzw);
    scan_kernel<<<RB, SCAN_THREADS, SCAN_SMEM_BYTES>>>(tokens, Whw);
    head_kernel<<<dim3(RV / 128, (RB * RT) / 128), HT>>>(E, out);
}

// round 13
// speedup vs baseline: 2.7870x; 1.2007x over previous
#include <cuda_runtime.h>

#define RB 64
#define RT 2048
#define RD 256
#define RV 256

// ---- device-global scratch (allocation-free per harness rules) ----
static __device__ float g_EWx[RV * RD];                 // E @ Wx^T   [tok][e]
static __device__ float g_EWg[RV * RD];                 // sigmoid(E @ Wz^T)
static __device__ float g_y[(size_t)RB * RT * RD];      // gated hidden states

typedef unsigned long long ull;

// packed fp32x2 FMA: 2 independent bit-exact fp32 FMAs per instruction
#define FMA2(acc, h, w) \
    asm("fma.rn.f32x2 %0, %1, %2, %0;" : "+l"(acc) : "l"(h), "l"(w))

__device__ __forceinline__ float f2lo(ull v) {
    return __uint_as_float((unsigned)v);
}
__device__ __forceinline__ float f2hi(ull v) {
    return __uint_as_float((unsigned)(v >> 32));
}

// ============================================================
// Kernel 1: token tables (V=256 -> projections depend only on token id)
// ============================================================
__global__ void precompute_kernel(const float* __restrict__ E,
                                  const float* __restrict__ Wxw,
                                  const float* __restrict__ Wzw) {
    __shared__ __align__(16) float er[RD];
    const int v = blockIdx.x & (RV - 1);
    const int which = blockIdx.x >> 8;
    const float* __restrict__ W = which ? Wzw : Wxw;
    const int e = threadIdx.x;
    er[e] = E[v * RD + e];
    __syncthreads();
    const float4* w4 = (const float4*)(W + e * RD);
    const float4* e4 = (const float4*)er;
    float acc = 0.f;
#pragma unroll 16
    for (int q = 0; q < RD / 4; q++) {
        float4 a = e4[q];
        float4 b = w4[q];
        acc += a.x * b.x; acc += a.y * b.y; acc += a.z * b.z; acc += a.w * b.w;
    }
    if (which) g_EWg[v * RD + e] = 1.f / (1.f + expf(-acc));
    else       g_EWx[v * RD + e] = acc;
}

// ============================================================
// Kernel 2: sequential scan, 2-CTA cluster per batch element.
// (EXACT R4 version — best measured scan component. Do not touch.)
// ============================================================
#define SCAN_THREADS 512
#define SCAN_PAD_BYTES (120 * 1024)   // occupancy limiter: 1 CTA/SM

__device__ __forceinline__ float tanh_acc(float x) {
    x = fminf(fmaxf(x, -15.f), 15.f);
    float e = __expf(2.f * x);
    return (e - 1.f) / (e + 1.f);
}

__device__ __forceinline__ unsigned smem_u32(const void* p) {
    return (unsigned)__cvta_generic_to_shared(p);
}

__global__ __launch_bounds__(SCAN_THREADS, 1) __cluster_dims__(2, 1, 1)
void scan_kernel(const int* __restrict__ tokens, const float* __restrict__ Whw) {
    __shared__ __align__(16) float sm_h[128];          // own half of h
    __shared__ __align__(16) float sm_ps[2 * RD];      // partials [kc][j]
    __shared__ __align__(16) float sm_recv[2][128];    // peer partial, dbl-buf
    __shared__ __align__(8)  unsigned long long mbar[2];
    extern __shared__ float sm_pad[];                  // unused (occupancy)

    const int b    = blockIdx.x >> 1;
    const int c    = blockIdx.x & 1;       // cluster rank
    const int peer = c ^ 1;
    const int t  = threadIdx.x;
    const int j  = t & (RD - 1);
    const int kc = t >> 8;                 // 0 or 1

    // ---- init mbarriers (count = 128 arrivals per phase) ----
    if (t == 0) {
        unsigned m0 = smem_u32(&mbar[0]);
        unsigned m1 = smem_u32(&mbar[1]);
        asm volatile("mbarrier.init.shared.b64 [%0], 128;" :: "r"(m0) : "memory");
        asm volatile("mbarrier.init.shared.b64 [%0], 128;" :: "r"(m1) : "memory");
    }
    if (t < 128) sm_h[t] = 0.f;
    __syncthreads();
    // cluster barrier: peers' mbarriers must be live before any remote arrive
    asm volatile("barrier.cluster.arrive.aligned;" ::: "memory");
    asm volatile("barrier.cluster.wait.aligned;"   ::: "memory");

    // ---- load my Wh[j][c*128 + kc*64 .. +64) slice into registers ----
    float whr[64];
    {
        const float* wrow = Whw + j * RD + c * 128 + kc * 64;
#pragma unroll
        for (int q = 0; q < 16; q++) {
            float4 vv = *(const float4*)(wrow + 4 * q);
            whr[4 * q + 0] = vv.x; whr[4 * q + 1] = vv.y;
            whr[4 * q + 2] = vv.z; whr[4 * q + 3] = vv.w;
        }
    }

    // remote addresses in peer's SMEM
    unsigned rmbar[2], rrecv[2];
    {
        unsigned a0 = smem_u32(&mbar[0]), a1 = smem_u32(&mbar[1]);
        asm("mapa.shared::cluster.u32 %0, %1, %2;" : "=r"(rmbar[0]) : "r"(a0), "r"(peer));
        asm("mapa.shared::cluster.u32 %0, %1, %2;" : "=r"(rmbar[1]) : "r"(a1), "r"(peer));
        if (t < 128) {
            unsigned b0 = smem_u32(&sm_recv[0][t]);
            unsigned b1 = smem_u32(&sm_recv[1][t]);
            asm("mapa.shared::cluster.u32 %0, %1, %2;" : "=r"(rrecv[0]) : "r"(b0), "r"(peer));
            asm("mapa.shared::cluster.u32 %0, %1, %2;" : "=r"(rrecv[1]) : "r"(b1), "r"(peer));
        }
    }
    const unsigned lmbar0 = smem_u32(&mbar[0]);
    const unsigned lmbar1 = smem_u32(&mbar[1]);

    const int*   tb = tokens + b * RT;
    float*       yb = g_y + (size_t)b * RT * RD;
    const float* hb = sm_h + kc * 64;
    const int    own0  = c * 128;          // my j/k base
    const int    peer0 = peer * 128;

    int ph0 = 0, ph1 = 0;                  // phase parity per buffer
    int tok = tb[0];
    for (int step = 0; step < RT; step++) {
        // prefetch token-indexed rows (hidden under matvec)
        float wxv = 0.f, gv = 0.f;
        if (t < 128) {
            wxv = __ldg(g_EWx + tok * RD + own0 + t);
            gv  = __ldg(g_EWg + tok * RD + own0 + t);
        }
        const int ntok = (step + 1 < RT) ? tb[step + 1] : 0;

        // register matvec: 64 FMAs over my K chunk
        float a0 = 0.f, a1 = 0.f, a2 = 0.f, a3 = 0.f;
#pragma unroll
        for (int q = 0; q < 16; q++) {
            float4 hv = *(const float4*)(hb + 4 * q);   // warp-broadcast LDS
            a0 += hv.x * whr[4 * q + 0];
            a1 += hv.y * whr[4 * q + 1];
            a2 += hv.z * whr[4 * q + 2];
            a3 += hv.w * whr[4 * q + 3];
        }
        sm_ps[(kc << 8) + j] = (a0 + a1) + (a2 + a3);
        __syncthreads();

        const int buf = step & 1;
        const unsigned lmb = buf ? lmbar1 : lmbar0;
        float own_p = 0.f;
        if (t < 128) {
            // send peer its half of my partial, release-arrive on peer mbar
            float ps = sm_ps[peer0 + t] + sm_ps[RD + peer0 + t];
            asm volatile("st.shared::cluster.f32 [%0], %1;"
                         :: "r"(rrecv[buf]), "f"(ps) : "memory");
            asm volatile("mbarrier.arrive.release.cluster.shared::cluster.b64 _, [%0];"
                         :: "r"(rmbar[buf]) : "memory");
            own_p = sm_ps[own0 + t] + sm_ps[RD + own0 + t];
            // wait for the peer's 128 arrivals (acquire orders its stores)
            int par = buf ? ph1 : ph0;
            unsigned done;
            do {
                asm volatile(
                    "{.reg .pred p;\n\t"
                    "mbarrier.try_wait.parity.acquire.cluster.shared::cta.b64 p, [%1], %2, 0x989680;\n\t"
                    "selp.b32 %0, 1, 0, p;}"
                    : "=r"(done) : "r"(lmb), "r"((unsigned)par) : "memory");
            } while (!done);
            float hn = tanh_acc(wxv + own_p + sm_recv[buf][t]);
            sm_h[t] = hn;
            yb[(size_t)step * RD + own0 + t] = hn * gv;   // coalesced 512B
        }
        if (buf) ph1 ^= 1; else ph0 ^= 1;
        __syncthreads();
        tok = ntok;
    }

    // drain: no CTA exits while the peer may still arrive on its mbars
    asm volatile("barrier.cluster.arrive.aligned;" ::: "memory");
    asm volatile("barrier.cluster.wait.aligned;"   ::: "memory");
    (void)sm_pad;
}

// ============================================================
// Kernel 3: tied head.  out[m][v] = sum_d Y[m][d] * E[v][d]
// 128x128x16 smem-tiled GEMM, 8x8 microtiles, FFMA2 inner product.
// (The ONLY change vs the 2359us R4 build — isolates headFF2 vs headF32.)
// ============================================================
#define HT 256
__global__ __launch_bounds__(HT, 2)
void head_kernel(const float* __restrict__ E, float* __restrict__ out) {
    __shared__ __align__(16) float As[16][128 + 4];
    __shared__ __align__(16) float Bs[16][128 + 4];
    const float* __restrict__ Y = g_y;
    const int m0 = blockIdx.y * 128;
    const int n0 = blockIdx.x * 128;
    const int tid = threadIdx.x;
    const int tx = tid & 15, ty = tid >> 4;

    ull cd[8][4];                          // 8 rows x 4 packed col-pairs
#pragma unroll
    for (int i = 0; i < 8; i++)
#pragma unroll
        for (int jj = 0; jj < 4; jj++) cd[i][jj] = 0ull;

    for (int kk = 0; kk < RD; kk += 16) {
#pragma unroll
        for (int l = 0; l < 2; l++) {
            int idx = tid + l * HT;
            int m   = idx >> 2;
            int kq  = idx & 3;
            float4 av = *(const float4*)(Y + (size_t)(m0 + m) * RD + kk + kq * 4);
            As[kq * 4 + 0][m] = av.x; As[kq * 4 + 1][m] = av.y;
            As[kq * 4 + 2][m] = av.z; As[kq * 4 + 3][m] = av.w;
            float4 bv = *(const float4*)(E + (size_t)(n0 + m) * RD + kk + kq * 4);
            Bs[kq * 4 + 0][m] = bv.x; Bs[kq * 4 + 1][m] = bv.y;
            Bs[kq * 4 + 2][m] = bv.z; Bs[kq * 4 + 3][m] = bv.w;
        }
        __syncthreads();
#pragma unroll
        for (int k = 0; k < 16; k++) {
            float a[8];
            *(float4*)(a)     = *(const float4*)(&As[k][ty * 8]);
            *(float4*)(a + 4) = *(const float4*)(&As[k][ty * 8 + 4]);
            ulonglong2 b01 = *(const ulonglong2*)(&Bs[k][tx * 8]);
            ulonglong2 b23 = *(const ulonglong2*)(&Bs[k][tx * 8 + 4]);
            ull bp0 = b01.x, bp1 = b01.y;
            ull bp2 = b23.x, bp3 = b23.y;
#pragma unroll
            for (int i = 0; i < 8; i++) {
                ull ad;
                unsigned au = __float_as_uint(a[i]);
                asm("mov.b64 %0, {%1, %1};" : "=l"(ad) : "r"(au));
                FMA2(cd[i][0], ad, bp0);
                FMA2(cd[i][1], ad, bp1);
                FMA2(cd[i][2], ad, bp2);
                FMA2(cd[i][3], ad, bp3);
            }
        }
        __syncthreads();
    }
#pragma unroll
    for (int i = 0; i < 8; i++) {
        float* orow = out + (size_t)(m0 + ty * 8 + i) * RV + n0 + tx * 8;
        *(float4*)(orow)     = make_float4(f2lo(cd[i][0]), f2hi(cd[i][0]),
                                           f2lo(cd[i][1]), f2hi(cd[i][1]));
        *(float4*)(orow + 4) = make_float4(f2lo(cd[i][2]), f2hi(cd[i][2]),
                                           f2lo(cd[i][3]), f2hi(cd[i][3]));
    }
}

// ============================================================
extern "C" void kernel_launch(void* const* d_in, const int* in_sizes, int n_in,
                              void* d_out, int out_size) {
    const int*   tokens = (const int*)  d_in[0];
    const float* E      = (const float*)d_in[1];
    const float* Wxw    = (const float*)d_in[2];
    const float* Whw    = (const float*)d_in[3];
    const float* Wzw    = (const float*)d_in[4];
    float* out = (float*)d_out;

    cudaFuncSetAttribute(scan_kernel,
                         cudaFuncAttributeMaxDynamicSharedMemorySize,
                         SCAN_PAD_BYTES);

    precompute_kernel<<<2 * RV, RD>>>(E, Wxw, Wzw);
    scan_kernel<<<2 * RB, SCAN_THREADS, SCAN_PAD_BYTES>>>(tokens, Whw);
    head_kernel<<<dim3(RV / 128, (RB * RT) / 128), HT>>>(E, out);
}

// round 16
// speedup vs baseline: 2.9068x; 1.0430x over previous
#include <cuda_runtime.h>
#include <cuda_bf16.h>
#include <mma.h>

#define RB 64
#define RT 2048
#define RD 256
#define RV 256

typedef unsigned long long ull;
using namespace nvcuda;

// ---- device-global scratch (allocation-free per harness rules) ----
static __device__ float g_EWx[RV * RD];                    // E @ Wx^T   [tok][e]
static __device__ float g_EWg[RV * RD];                    // sigmoid(E @ Wz^T)
static __device__ __nv_bfloat16 g_yhi[(size_t)RB * RT * RD];  // y split hi
static __device__ __nv_bfloat16 g_ylo[(size_t)RB * RT * RD];  // y split lo
static __device__ __nv_bfloat16 g_Ehi[RV * RD];            // E split hi
static __device__ __nv_bfloat16 g_Elo[RV * RD];            // E split lo

__device__ __forceinline__ unsigned smem_u32(const void* p) {
    return (unsigned)__cvta_generic_to_shared(p);
}

// ============================================================
// Kernel 1: token tables (V=256 -> projections depend only on token id)
// ============================================================
__global__ void precompute_kernel(const float* __restrict__ E,
                                  const float* __restrict__ Wxw,
                                  const float* __restrict__ Wzw) {
    __shared__ __align__(16) float er[RD];
    const int v = blockIdx.x & (RV - 1);
    const int which = blockIdx.x >> 8;
    const float* __restrict__ W = which ? Wzw : Wxw;
    const int e = threadIdx.x;
    er[e] = E[v * RD + e];
    __syncthreads();
    const float4* w4 = (const float4*)(W + e * RD);
    const float4* e4 = (const float4*)er;
    float acc = 0.f;
#pragma unroll 16
    for (int q = 0; q < RD / 4; q++) {
        float4 a = e4[q];
        float4 b = w4[q];
        acc += a.x * b.x; acc += a.y * b.y; acc += a.z * b.z; acc += a.w * b.w;
    }
    if (which) g_EWg[v * RD + e] = 1.f / (1.f + expf(-acc));
    else       g_EWx[v * RD + e] = acc;
}

// ============================================================
// Kernel 1b: split E into bf16 hi/lo
// ============================================================
__global__ void esplit_kernel(const float* __restrict__ E) {
    const int i = blockIdx.x * 256 + threadIdx.x;
    float v = E[i];
    __nv_bfloat16 h = __float2bfloat16(v);
    g_Ehi[i] = h;
    g_Elo[i] = __float2bfloat16(v - __bfloat162float(h));
}

// ============================================================
// Kernel 2: sequential scan, 2-CTA cluster per batch element.
// (R4 version — best measured scan. Only change: y stored as bf16 hi/lo.)
// ============================================================
#define SCAN_THREADS 512
#define SCAN_PAD_BYTES (120 * 1024)   // occupancy limiter: 1 CTA/SM

__device__ __forceinline__ float tanh_acc(float x) {
    x = fminf(fmaxf(x, -15.f), 15.f);
    float e = __expf(2.f * x);
    return (e - 1.f) / (e + 1.f);
}

__global__ __launch_bounds__(SCAN_THREADS, 1) __cluster_dims__(2, 1, 1)
void scan_kernel(const int* __restrict__ tokens, const float* __restrict__ Whw) {
    __shared__ __align__(16) float sm_h[128];          // own half of h
    __shared__ __align__(16) float sm_ps[2 * RD];      // partials [kc][j]
    __shared__ __align__(16) float sm_recv[2][128];    // peer partial, dbl-buf
    __shared__ __align__(8)  unsigned long long mbar[2];
    extern __shared__ float sm_pad[];                  // unused (occupancy)

    const int b    = blockIdx.x >> 1;
    const int c    = blockIdx.x & 1;       // cluster rank
    const int peer = c ^ 1;
    const int t  = threadIdx.x;
    const int j  = t & (RD - 1);
    const int kc = t >> 8;                 // 0 or 1

    if (t == 0) {
        unsigned m0 = smem_u32(&mbar[0]);
        unsigned m1 = smem_u32(&mbar[1]);
        asm volatile("mbarrier.init.shared.b64 [%0], 128;" :: "r"(m0) : "memory");
        asm volatile("mbarrier.init.shared.b64 [%0], 128;" :: "r"(m1) : "memory");
    }
    if (t < 128) sm_h[t] = 0.f;
    __syncthreads();
    asm volatile("barrier.cluster.arrive.aligned;" ::: "memory");
    asm volatile("barrier.cluster.wait.aligned;"   ::: "memory");

    float whr[64];
    {
        const float* wrow = Whw + j * RD + c * 128 + kc * 64;
#pragma unroll
        for (int q = 0; q < 16; q++) {
            float4 vv = *(const float4*)(wrow + 4 * q);
            whr[4 * q + 0] = vv.x; whr[4 * q + 1] = vv.y;
            whr[4 * q + 2] = vv.z; whr[4 * q + 3] = vv.w;
        }
    }

    unsigned rmbar[2], rrecv[2];
    {
        unsigned a0 = smem_u32(&mbar[0]), a1 = smem_u32(&mbar[1]);
        asm("mapa.shared::cluster.u32 %0, %1, %2;" : "=r"(rmbar[0]) : "r"(a0), "r"(peer));
        asm("mapa.shared::cluster.u32 %0, %1, %2;" : "=r"(rmbar[1]) : "r"(a1), "r"(peer));
        if (t < 128) {
            unsigned b0 = smem_u32(&sm_recv[0][t]);
            unsigned b1 = smem_u32(&sm_recv[1][t]);
            asm("mapa.shared::cluster.u32 %0, %1, %2;" : "=r"(rrecv[0]) : "r"(b0), "r"(peer));
            asm("mapa.shared::cluster.u32 %0, %1, %2;" : "=r"(rrecv[1]) : "r"(b1), "r"(peer));
        }
    }
    const unsigned lmbar0 = smem_u32(&mbar[0]);
    const unsigned lmbar1 = smem_u32(&mbar[1]);

    const int*   tb = tokens + b * RT;
    const float* hb = sm_h + kc * 64;
    const int    own0  = c * 128;
    const int    peer0 = peer * 128;
    __nv_bfloat16* yhb = g_yhi + (size_t)b * RT * RD;
    __nv_bfloat16* ylb = g_ylo + (size_t)b * RT * RD;

    int ph0 = 0, ph1 = 0;
    int tok = tb[0];
    for (int step = 0; step < RT; step++) {
        float wxv = 0.f, gv = 0.f;
        if (t < 128) {
            wxv = __ldg(g_EWx + tok * RD + own0 + t);
            gv  = __ldg(g_EWg + tok * RD + own0 + t);
        }
        const int ntok = (step + 1 < RT) ? tb[step + 1] : 0;

        float a0 = 0.f, a1 = 0.f, a2 = 0.f, a3 = 0.f;
#pragma unroll
        for (int q = 0; q < 16; q++) {
            float4 hv = *(const float4*)(hb + 4 * q);   // warp-broadcast LDS
            a0 += hv.x * whr[4 * q + 0];
            a1 += hv.y * whr[4 * q + 1];
            a2 += hv.z * whr[4 * q + 2];
            a3 += hv.w * whr[4 * q + 3];
        }
        sm_ps[(kc << 8) + j] = (a0 + a1) + (a2 + a3);
        __syncthreads();

        const int buf = step & 1;
        const unsigned lmb = buf ? lmbar1 : lmbar0;
        float own_p = 0.f;
        if (t < 128) {
            float ps = sm_ps[peer0 + t] + sm_ps[RD + peer0 + t];
            asm volatile("st.shared::cluster.f32 [%0], %1;"
                         :: "r"(rrecv[buf]), "f"(ps) : "memory");
            asm volatile("mbarrier.arrive.release.cluster.shared::cluster.b64 _, [%0];"
                         :: "r"(rmbar[buf]) : "memory");
            own_p = sm_ps[own0 + t] + sm_ps[RD + own0 + t];
            int par = buf ? ph1 : ph0;
            unsigned done;
            do {
                asm volatile(
                    "{.reg .pred p;\n\t"
                    "mbarrier.try_wait.parity.acquire.cluster.shared::cta.b64 p, [%1], %2, 0x989680;\n\t"
                    "selp.b32 %0, 1, 0, p;}"
                    : "=r"(done) : "r"(lmb), "r"((unsigned)par) : "memory");
            } while (!done);
            float hn = tanh_acc(wxv + own_p + sm_recv[buf][t]);
            sm_h[t] = hn;
            float yv = hn * gv;
            __nv_bfloat16 hi = __float2bfloat16(yv);
            size_t yi = (size_t)step * RD + own0 + t;
            yhb[yi] = hi;
            ylb[yi] = __float2bfloat16(yv - __bfloat162float(hi));
        }
        if (buf) ph1 ^= 1; else ph0 ^= 1;
        __syncthreads();
        tok = ntok;
    }

    asm volatile("barrier.cluster.arrive.aligned;" ::: "memory");
    asm volatile("barrier.cluster.wait.aligned;"   ::: "memory");
    (void)sm_pad;
}

// ============================================================
// Kernel 3: tied head on tensor cores via portable wmma (HMMA).
// out[m][v] = sum_d y[m][d]*E[v][d]
//  = yhi*Ehi + ylo*Ehi + yhi*Elo   (+O(2^-18); fp32 accum in registers)
// CTA tile 128x128 (8 warps x 32x64 warp tiles), K staged in 32-wide
// SMEM chunks (row stride 40 bf16 -> conflict-free LDSM).
// grid = (NV/128, M/128) = (2, 1024).
// ============================================================
#define HKC 32
#define HPAD 8
#define HLD (HKC + HPAD)
__global__ __launch_bounds__(256, 2)
void head_wmma_kernel(float* __restrict__ out) {
    __shared__ __nv_bfloat16 As[128][HLD];
    __shared__ __nv_bfloat16 Bs[128][HLD];
    const int tid = threadIdx.x, wid = tid >> 5;
    const size_t m0 = (size_t)blockIdx.y * 128;
    const int n0 = blockIdx.x * 128;
    const int wm = wid & 3;            // warp row tile: rows wm*32..+32
    const int wn = wid >> 2;           // warp col tile: cols wn*64..+64

    wmma::fragment<wmma::accumulator, 16, 16, 16, float> acc[2][4];
#pragma unroll
    for (int i = 0; i < 2; i++)
#pragma unroll
        for (int jj = 0; jj < 4; jj++) wmma::fill_fragment(acc[i][jj], 0.f);

    for (int seg = 0; seg < 3; seg++) {
        const __nv_bfloat16* __restrict__ Aseg =
            (seg == 1) ? (g_ylo + m0 * RD) : (g_yhi + m0 * RD);
        const __nv_bfloat16* __restrict__ Bseg =
            ((seg == 2) ? g_Elo : g_Ehi) + n0 * RD;
        for (int kc = 0; kc < RD; kc += HKC) {
            __syncthreads();           // previous chunk fully consumed
            // stage A and B chunks: 128 rows x 32 bf16 each (8B per thread-op)
#pragma unroll
            for (int l = 0; l < 4; l++) {
                int i = tid + l * 256;                 // 0..1023
                int row = i >> 3;
                int cg  = (i & 7) * 4;
                *(ull*)&As[row][cg] = *(const ull*)(Aseg + (size_t)row * RD + kc + cg);
                *(ull*)&Bs[row][cg] = *(const ull*)(Bseg + (size_t)row * RD + kc + cg);
            }
            __syncthreads();
#pragma unroll
            for (int ks = 0; ks < HKC; ks += 16) {
                wmma::fragment<wmma::matrix_a, 16, 16, 16, __nv_bfloat16,
                               wmma::row_major> af[2];
                wmma::fragment<wmma::matrix_b, 16, 16, 16, __nv_bfloat16,
                               wmma::col_major> bf[4];
#pragma unroll
                for (int i = 0; i < 2; i++)
                    wmma::load_matrix_sync(af[i], &As[wm * 32 + i * 16][ks], HLD);
#pragma unroll
                for (int jj = 0; jj < 4; jj++)
                    wmma::load_matrix_sync(bf[jj], &Bs[wn * 64 + jj * 16][ks], HLD);
#pragma unroll
                for (int i = 0; i < 2; i++)
#pragma unroll
                    for (int jj = 0; jj < 4; jj++)
                        wmma::mma_sync(acc[i][jj], af[i], bf[jj], acc[i][jj]);
            }
        }
    }

#pragma unroll
    for (int i = 0; i < 2; i++)
#pragma unroll
        for (int jj = 0; jj < 4; jj++)
            wmma::store_matrix_sync(
                out + (m0 + wm * 32 + i * 16) * RV + n0 + wn * 64 + jj * 16,
                acc[i][jj], RV, wmma::mem_row_major);
}

// ============================================================
extern "C" void kernel_launch(void* const* d_in, const int* in_sizes, int n_in,
                              void* d_out, int out_size) {
    const int*   tokens = (const int*)  d_in[0];
    const float* E      = (const float*)d_in[1];
    const float* Wxw    = (const float*)d_in[2];
    const float* Whw    = (const float*)d_in[3];
    const float* Wzw    = (const float*)d_in[4];
    float* out = (float*)d_out;

    cudaFuncSetAttribute(scan_kernel,
                         cudaFuncAttributeMaxDynamicSharedMemorySize,
                         SCAN_PAD_BYTES);

    precompute_kernel<<<2 * RV, RD>>>(E, Wxw, Wzw);
    esplit_kernel<<<RV, RD>>>(E);
    scan_kernel<<<2 * RB, SCAN_THREADS, SCAN_PAD_BYTES>>>(tokens, Whw);
    head_wmma_kernel<<<dim3(RV / 128, (RB * RT) / 128), 256>>>(out);
}